// round 3
// baseline (speedup 1.0000x reference)
#include <cuda_runtime.h>
#include <cuda_bf16.h>
#include <cstdint>

#define DIMN 640
#define BATCH 64
#define MSP 100
#define TRI 205120           // 640*641/2
#define LDA 108              // smem row stride for operands
#define LDT 132              // smem row stride for staged output tile
#define SQRT_EPS 0.0031622776601683794f

// -------- scratch (no allocations allowed) --------
__device__ float g_d[BATCH * DIMN];       // squared norms (exact fp32)
__device__ float g_rowsum[BATCH * DIMN];  // full-row sums of dcov
__device__ float g_total[BATCH];          // grand sums

__device__ __forceinline__ unsigned f2tf32(float f) {
    unsigned u;
    asm("cvt.rna.tf32.f32 %0, %1;" : "=r"(u) : "f"(f));
    return u;
}
__device__ __forceinline__ float asqrt(float x) {
    float r;
    asm("sqrt.approx.f32 %0, %1;" : "=f"(r) : "f"(x));
    return r;
}
__device__ __forceinline__ void mma_tf32(float c[4], const unsigned a[4], const unsigned b[2]) {
    asm volatile(
        "mma.sync.aligned.m16n8k8.row.col.f32.tf32.tf32.f32 "
        "{%0,%1,%2,%3}, {%4,%5,%6,%7}, {%8,%9}, {%0,%1,%2,%3};"
        : "+f"(c[0]), "+f"(c[1]), "+f"(c[2]), "+f"(c[3])
        : "r"(a[0]), "r"(a[1]), "r"(a[2]), "r"(a[3]), "r"(b[0]), "r"(b[1]));
}

// ---------------- Kernel 0: exact squared norms + zero rowsums ----------------
__global__ void k_norms(const float* __restrict__ x) {
    int warp = blockIdx.x * 8 + (threadIdx.x >> 5);
    int lane = threadIdx.x & 31;
    if (warp >= BATCH * DIMN) return;
    const float* p = x + (size_t)warp * MSP;
    float s = 0.f;
    for (int m = lane; m < MSP; m += 32) {
        float v = p[m];
        s = fmaf(v, v, s);
    }
    #pragma unroll
    for (int o = 16; o > 0; o >>= 1) s += __shfl_xor_sync(0xffffffffu, s, o);
    if (lane == 0) {
        g_d[warp] = s;
        g_rowsum[warp] = 0.f;
    }
}

// ---------------- Kernel 1: tf32 Gram tiles + fused BDC epilogue ----------------
__global__ void __launch_bounds__(256, 1)
k_bdc(const float* __restrict__ x, const float* __restrict__ tptr, float* __restrict__ out) {
    extern __shared__ float smem[];
    float* As = smem;                 // [128][LDA]
    float* Bs = smem + 128 * LDA;     // [128][LDA]
    float* Ts = smem;                 // staged output tile [128][LDT], reused after MMA
    __shared__ float rssh[128];
    __shared__ float cssh[128];

    const int tid = threadIdx.x;
    int b = blockIdx.x / 15;
    int p = blockIdx.x % 15;
    int ti = 0;
    while (p >= 5 - ti) { p -= 5 - ti; ti++; }
    int tj = ti + p;
    const bool diag = (ti == tj);

    // load tiles (tf32-converted), K padded with zeros to 104
    const float* xa = x + (size_t)(b * DIMN + ti * 128) * MSP;
    const float* xb = x + (size_t)(b * DIMN + tj * 128) * MSP;
    for (int idx = tid; idx < 128 * MSP; idx += 256) {
        int r = idx / MSP;
        int m = idx - r * MSP;
        As[r * LDA + m] = __uint_as_float(f2tf32(xa[idx]));
        Bs[r * LDA + m] = __uint_as_float(f2tf32(xb[idx]));
    }
    for (int idx = tid; idx < 128 * 4; idx += 256) {
        int r = idx >> 2, c = idx & 3;
        As[r * LDA + MSP + c] = 0.f;
        Bs[r * LDA + MSP + c] = 0.f;
    }
    if (tid < 128) rssh[tid] = 0.f;
    else cssh[tid - 128] = 0.f;
    __syncthreads();

    const int lane = tid & 31;
    const int w = tid >> 5;
    const int wm = (w >> 2) * 64;   // warp m-offset (2 warps in m)
    const int wn = (w & 3) * 32;    // warp n-offset (4 warps in n)
    const int g = lane >> 2;        // 0..7
    const int tg = lane & 3;        // 0..3

    float acc[4][4][4];
    #pragma unroll
    for (int am = 0; am < 4; am++)
        #pragma unroll
        for (int an = 0; an < 4; an++)
            #pragma unroll
            for (int v = 0; v < 4; v++) acc[am][an][v] = 0.f;

    #pragma unroll
    for (int ks = 0; ks < 13; ks++) {
        const int k0 = ks * 8;
        unsigned a[4][4], bf[4][2];
        #pragma unroll
        for (int am = 0; am < 4; am++) {
            const float* r0 = &As[(wm + am * 16 + g) * LDA + k0 + tg];
            const float* r1 = &As[(wm + am * 16 + g + 8) * LDA + k0 + tg];
            a[am][0] = __float_as_uint(r0[0]);
            a[am][1] = __float_as_uint(r1[0]);
            a[am][2] = __float_as_uint(r0[4]);
            a[am][3] = __float_as_uint(r1[4]);
        }
        #pragma unroll
        for (int an = 0; an < 4; an++) {
            const float* br = &Bs[(wn + an * 8 + g) * LDA + k0 + tg];
            bf[an][0] = __float_as_uint(br[0]);
            bf[an][1] = __float_as_uint(br[4]);
        }
        #pragma unroll
        for (int am = 0; am < 4; am++)
            #pragma unroll
            for (int an = 0; an < 4; an++) mma_tf32(acc[am][an], a[am], bf[an]);
    }

    // ---- epilogue: dcov transform, stage into smem tile ----
    const float s = expf(tptr[0]);
    float drow[8], dcol[8];
    const int rbase = b * DIMN + ti * 128 + wm;
    const int cbase = b * DIMN + tj * 128 + wn;
    #pragma unroll
    for (int am = 0; am < 4; am++) {
        drow[2 * am]     = g_d[rbase + am * 16 + g];
        drow[2 * am + 1] = g_d[rbase + am * 16 + g + 8];
    }
    #pragma unroll
    for (int an = 0; an < 4; an++) {
        dcol[2 * an]     = g_d[cbase + an * 8 + 2 * tg];
        dcol[2 * an + 1] = g_d[cbase + an * 8 + 2 * tg + 1];
    }

    float rp[8], cp[8];
    #pragma unroll
    for (int q = 0; q < 8; q++) { rp[q] = 0.f; cp[q] = 0.f; }

    __syncthreads();   // all warps done reading As/Bs; safe to overwrite with Ts

    #pragma unroll
    for (int am = 0; am < 4; am++) {
        #pragma unroll
        for (int an = 0; an < 4; an++) {
            #pragma unroll
            for (int v = 0; v < 4; v++) {
                const int hi = v >> 1, lo = v & 1;
                const int r = wm + am * 16 + g + hi * 8;   // local row in tile
                const int c = wn + an * 8 + 2 * tg + lo;   // local col in tile
                float q2 = drow[2 * am + hi] + dcol[2 * an + lo] - 2.f * acc[am][an][v];
                q2 = fmaxf(q2, 0.f);
                float val = asqrt(fmaf(q2, s, 1e-5f));
                if (diag) {
                    if (c == r) val = SQRT_EPS;
                    if (c > r) { rp[2 * am + hi] += val; cp[2 * an + lo] += val; }
                    else if (c == r) rp[2 * am + hi] += val;
                } else {
                    rp[2 * am + hi] += val;
                    cp[2 * an + lo] += val;
                }
                Ts[r * LDT + c] = val;
            }
        }
    }
    __syncthreads();

    // ---- coalesced stores from staged tile ----
    const int ob = b * TRI;
    const int lane128 = tid & 127;
    if (!diag) {
        #pragma unroll 4
        for (int r = tid >> 7; r < 128; r += 2) {
            const int gi = ti * 128 + r;
            const int gj = tj * 128 + lane128;
            const int rowoff = gi * (DIMN - 1) - ((gi * (gi - 1)) >> 1);  // row start minus gi
            out[ob + rowoff + gj] = Ts[r * LDT + lane128];
        }
    } else {
        #pragma unroll 4
        for (int r = tid >> 7; r < 128; r += 2) {
            const int gi = ti * 128 + r;
            const int rowoff = gi * (DIMN - 1) - ((gi * (gi - 1)) >> 1);
            const int c = r + lane128;
            if (c < 128)
                out[ob + rowoff + ti * 128 + c] = Ts[r * LDT + c];
        }
    }

    // ---- row/col sum reductions ----
    #pragma unroll
    for (int q = 0; q < 8; q++) {
        float r = rp[q];
        r += __shfl_xor_sync(0xffffffffu, r, 1);
        r += __shfl_xor_sync(0xffffffffu, r, 2);
        if (tg == 0) atomicAdd(&rssh[wm + (q >> 1) * 16 + g + (q & 1) * 8], r);
    }
    #pragma unroll
    for (int q = 0; q < 8; q++) {
        float c = cp[q];
        c += __shfl_xor_sync(0xffffffffu, c, 4);
        c += __shfl_xor_sync(0xffffffffu, c, 8);
        c += __shfl_xor_sync(0xffffffffu, c, 16);
        if (g == 0) atomicAdd(&cssh[wn + (q >> 1) * 8 + 2 * tg + (q & 1)], c);
    }
    __syncthreads();
    if (tid < 128) atomicAdd(&g_rowsum[b * DIMN + ti * 128 + tid], rssh[tid]);
    else atomicAdd(&g_rowsum[b * DIMN + tj * 128 + (tid - 128)], cssh[tid - 128]);
}

// ---------------- Kernel 2: per-batch grand totals ----------------
__global__ void k_total() {
    __shared__ float sh[256];
    const int b = blockIdx.x;
    const int tid = threadIdx.x;
    float s = 0.f;
    for (int i = tid; i < DIMN; i += 256) s += g_rowsum[b * DIMN + i];
    sh[tid] = s;
    __syncthreads();
    for (int o = 128; o > 0; o >>= 1) {
        if (tid < o) sh[tid] += sh[tid + o];
        __syncthreads();
    }
    if (tid == 0) g_total[b] = sh[0];
}

// ---------------- Kernel 3: double centering (balanced row pairs) ----------------
__device__ __forceinline__ void center_row(float* __restrict__ out, int b, int i,
                                           float total, float inv) {
    const int len = DIMN - i;
    const float a = total - g_rowsum[b * DIMN + i] * inv;
    float* p = out + (size_t)b * TRI + i * DIMN - ((i * (i - 1)) >> 1);
    const float* rs = &g_rowsum[b * DIMN + i];
    for (int k = threadIdx.x; k < len; k += 256)
        p[k] = p[k] - rs[k] * inv + a;
}

__global__ void __launch_bounds__(256)
k_center(float* __restrict__ out) {
    const int bid = blockIdx.x;
    const int b = bid / (DIMN / 2);
    const int pr = bid - b * (DIMN / 2);        // 0..319
    const float inv = 1.f / (float)DIMN;
    const float total = g_total[b] * (1.f / ((float)DIMN * (float)DIMN));
    center_row(out, b, pr, total, inv);
    center_row(out, b, DIMN - 1 - pr, total, inv);
}

extern "C" void kernel_launch(void* const* d_in, const int* in_sizes, int n_in,
                              void* d_out, int out_size) {
    const float* x = (const float*)d_in[0];
    const float* t = (const float*)d_in[1];
    float* out = (float*)d_out;

    const int smem = 2 * 128 * LDA * (int)sizeof(float);  // 110,592 B
    cudaFuncSetAttribute(k_bdc, cudaFuncAttributeMaxDynamicSharedMemorySize, smem);

    k_norms<<<(BATCH * DIMN) / 8, 256>>>(x);
    k_bdc<<<BATCH * 15, 256, smem>>>(x, t, out);
    k_total<<<BATCH, 256>>>();
    k_center<<<BATCH * (DIMN / 2), 256>>>(out);
}

// round 8
// speedup vs baseline: 1.0816x; 1.0816x over previous
#include <cuda_runtime.h>
#include <cuda_bf16.h>
#include <cstdint>

#define DIMN 640
#define BATCH 64
#define MSP 100
#define TRI 205120           // 640*641/2
#define LDA 108              // smem row stride for operands
#define LDT 132              // smem row stride for staged output tile
#define SQRT_EPS 0.0031622776601683794f

// -------- scratch (no allocations allowed) --------
__device__ float g_d[BATCH * DIMN];       // squared norms (exact fp32)
__device__ float g_rowsum[BATCH * DIMN];  // full-row sums of dcov
__device__ float g_total[BATCH];          // grand sums

__device__ __forceinline__ unsigned f2tf32(float f) {
    unsigned u;
    asm("cvt.rna.tf32.f32 %0, %1;" : "=r"(u) : "f"(f));
    return u;
}
__device__ __forceinline__ float asqrt(float x) {
    float r;
    asm("sqrt.approx.f32 %0, %1;" : "=f"(r) : "f"(x));
    return r;
}
__device__ __forceinline__ void mma_tf32(float c[4], const unsigned a[4], const unsigned b[2]) {
    asm volatile(
        "mma.sync.aligned.m16n8k8.row.col.f32.tf32.tf32.f32 "
        "{%0,%1,%2,%3}, {%4,%5,%6,%7}, {%8,%9}, {%0,%1,%2,%3};"
        : "+f"(c[0]), "+f"(c[1]), "+f"(c[2]), "+f"(c[3])
        : "r"(a[0]), "r"(a[1]), "r"(a[2]), "r"(a[3]), "r"(b[0]), "r"(b[1]));
}

// ---------------- Kernel 0: exact squared norms + zero rowsums ----------------
__global__ void k_norms(const float* __restrict__ x) {
    int warp = blockIdx.x * 8 + (threadIdx.x >> 5);
    int lane = threadIdx.x & 31;
    if (warp >= BATCH * DIMN) return;
    const float* p = x + (size_t)warp * MSP;
    float s = 0.f;
    for (int m = lane; m < MSP; m += 32) {
        float v = p[m];
        s = fmaf(v, v, s);
    }
    #pragma unroll
    for (int o = 16; o > 0; o >>= 1) s += __shfl_xor_sync(0xffffffffu, s, o);
    if (lane == 0) {
        g_d[warp] = s;
        g_rowsum[warp] = 0.f;
    }
}

// ---------------- Kernel 1: tf32 Gram tiles + fused BDC epilogue ----------------
__global__ void __launch_bounds__(256, 2)
k_bdc(const float* __restrict__ x, const float* __restrict__ tptr, float* __restrict__ out) {
    extern __shared__ float smem[];
    float* As = smem;                 // [128][LDA]
    float* Bs = smem + 128 * LDA;     // [128][LDA]
    float* Ts = smem;                 // staged output tile [128][LDT], reused after MMA
    __shared__ float rssh[128];
    __shared__ float cssh[128];

    const int tid = threadIdx.x;
    int b = blockIdx.x / 15;
    int p = blockIdx.x % 15;
    int ti = 0;
    while (p >= 5 - ti) { p -= 5 - ti; ti++; }
    int tj = ti + p;
    const bool diag = (ti == tj);

    // load tiles (tf32-converted), K padded with zeros to 104
    const float* xa = x + (size_t)(b * DIMN + ti * 128) * MSP;
    const float* xb = x + (size_t)(b * DIMN + tj * 128) * MSP;
    for (int idx = tid; idx < 128 * MSP; idx += 256) {
        int r = idx / MSP;
        int m = idx - r * MSP;
        As[r * LDA + m] = __uint_as_float(f2tf32(xa[idx]));
        if (!diag) Bs[r * LDA + m] = __uint_as_float(f2tf32(xb[idx]));
    }
    for (int idx = tid; idx < 128 * 4; idx += 256) {
        int r = idx >> 2, c = idx & 3;
        As[r * LDA + MSP + c] = 0.f;
        if (!diag) Bs[r * LDA + MSP + c] = 0.f;
    }
    if (tid < 128) rssh[tid] = 0.f;
    else cssh[tid - 128] = 0.f;
    __syncthreads();

    const float* Bse = diag ? As : Bs;

    const int lane = tid & 31;
    const int w = tid >> 5;
    const int wm = (w >> 2) * 64;   // warp m-offset (2 warps in m)
    const int wn = (w & 3) * 32;    // warp n-offset (4 warps in n)
    const int g = lane >> 2;        // 0..7
    const int tg = lane & 3;        // 0..3

    float acc[4][4][4];
    #pragma unroll
    for (int am = 0; am < 4; am++)
        #pragma unroll
        for (int an = 0; an < 4; an++)
            #pragma unroll
            for (int v = 0; v < 4; v++) acc[am][an][v] = 0.f;

    #pragma unroll
    for (int ks = 0; ks < 13; ks++) {
        const int k0 = ks * 8;
        unsigned a[4][4], bf[4][2];
        #pragma unroll
        for (int am = 0; am < 4; am++) {
            const float* r0 = &As[(wm + am * 16 + g) * LDA + k0 + tg];
            const float* r1 = &As[(wm + am * 16 + g + 8) * LDA + k0 + tg];
            a[am][0] = __float_as_uint(r0[0]);
            a[am][1] = __float_as_uint(r1[0]);
            a[am][2] = __float_as_uint(r0[4]);
            a[am][3] = __float_as_uint(r1[4]);
        }
        #pragma unroll
        for (int an = 0; an < 4; an++) {
            const float* br = &Bse[(wn + an * 8 + g) * LDA + k0 + tg];
            bf[an][0] = __float_as_uint(br[0]);
            bf[an][1] = __float_as_uint(br[4]);
        }
        #pragma unroll
        for (int am = 0; am < 4; am++)
            #pragma unroll
            for (int an = 0; an < 4; an++) mma_tf32(acc[am][an], a[am], bf[an]);
    }

    // ---- epilogue: dcov transform, stage into smem tile ----
    const float s = expf(tptr[0]);
    float drow[8], dcol[8];
    const int rbase = b * DIMN + ti * 128 + wm;
    const int cbase = b * DIMN + tj * 128 + wn;
    #pragma unroll
    for (int am = 0; am < 4; am++) {
        drow[2 * am]     = g_d[rbase + am * 16 + g];
        drow[2 * am + 1] = g_d[rbase + am * 16 + g + 8];
    }
    #pragma unroll
    for (int an = 0; an < 4; an++) {
        dcol[2 * an]     = g_d[cbase + an * 8 + 2 * tg];
        dcol[2 * an + 1] = g_d[cbase + an * 8 + 2 * tg + 1];
    }

    float rp[8], cp[8];
    #pragma unroll
    for (int q = 0; q < 8; q++) { rp[q] = 0.f; cp[q] = 0.f; }

    __syncthreads();   // all warps done reading As/Bs; safe to overwrite with Ts

    #pragma unroll
    for (int am = 0; am < 4; am++) {
        #pragma unroll
        for (int an = 0; an < 4; an++) {
            #pragma unroll
            for (int v = 0; v < 4; v++) {
                const int hi = v >> 1, lo = v & 1;
                const int r = wm + am * 16 + g + hi * 8;   // local row in tile
                const int c = wn + an * 8 + 2 * tg + lo;   // local col in tile
                float q2 = drow[2 * am + hi] + dcol[2 * an + lo] - 2.f * acc[am][an][v];
                q2 = fmaxf(q2, 0.f);
                float val = asqrt(fmaf(q2, s, 1e-5f));
                if (diag) {
                    if (c == r) val = SQRT_EPS;
                    if (c > r) { rp[2 * am + hi] += val; cp[2 * an + lo] += val; }
                    else if (c == r) rp[2 * am + hi] += val;
                } else {
                    rp[2 * am + hi] += val;
                    cp[2 * an + lo] += val;
                }
                Ts[r * LDT + c] = val;
            }
        }
    }
    __syncthreads();

    // ---- coalesced stores from staged tile ----
    const int ob = b * TRI;
    const int lane128 = tid & 127;
    if (!diag) {
        #pragma unroll 4
        for (int r = tid >> 7; r < 128; r += 2) {
            const int gi = ti * 128 + r;
            const int gj = tj * 128 + lane128;
            const int rowoff = gi * (DIMN - 1) - ((gi * (gi - 1)) >> 1);  // row start minus gi
            out[ob + rowoff + gj] = Ts[r * LDT + lane128];
        }
    } else {
        #pragma unroll 4
        for (int r = tid >> 7; r < 128; r += 2) {
            const int gi = ti * 128 + r;
            const int rowoff = gi * (DIMN - 1) - ((gi * (gi - 1)) >> 1);
            const int c = r + lane128;
            if (c < 128)
                out[ob + rowoff + ti * 128 + c] = Ts[r * LDT + c];
        }
    }

    // ---- row/col sum reductions ----
    #pragma unroll
    for (int q = 0; q < 8; q++) {
        float r = rp[q];
        r += __shfl_xor_sync(0xffffffffu, r, 1);
        r += __shfl_xor_sync(0xffffffffu, r, 2);
        if (tg == 0) atomicAdd(&rssh[wm + (q >> 1) * 16 + g + (q & 1) * 8], r);
    }
    #pragma unroll
    for (int q = 0; q < 8; q++) {
        float c = cp[q];
        c += __shfl_xor_sync(0xffffffffu, c, 4);
        c += __shfl_xor_sync(0xffffffffu, c, 8);
        c += __shfl_xor_sync(0xffffffffu, c, 16);
        if (g == 0) atomicAdd(&cssh[wn + (q >> 1) * 8 + 2 * tg + (q & 1)], c);
    }
    __syncthreads();
    if (tid < 128) atomicAdd(&g_rowsum[b * DIMN + ti * 128 + tid], rssh[tid]);
    else atomicAdd(&g_rowsum[b * DIMN + tj * 128 + (tid - 128)], cssh[tid - 128]);
}

// ---------------- Kernel 2: per-batch grand totals ----------------
__global__ void k_total() {
    __shared__ float sh[256];
    const int b = blockIdx.x;
    const int tid = threadIdx.x;
    float s = 0.f;
    for (int i = tid; i < DIMN; i += 256) s += g_rowsum[b * DIMN + i];
    sh[tid] = s;
    __syncthreads();
    for (int o = 128; o > 0; o >>= 1) {
        if (tid < o) sh[tid] += sh[tid + o];
        __syncthreads();
    }
    if (tid == 0) g_total[b] = sh[0];
}

// ---------------- Kernel 3: double centering, 8 blocks/batch ----------------
__global__ void __launch_bounds__(256)
k_center(float* __restrict__ out) {
    __shared__ float rs[DIMN];
    const int b = blockIdx.x >> 3;
    const int blk = blockIdx.x & 7;
    const int tid = threadIdx.x;
    const float inv = 1.f / (float)DIMN;
    for (int i = tid; i < DIMN; i += 256) rs[i] = g_rowsum[b * DIMN + i] * inv;
    __syncthreads();
    const float total = g_total[b] * (1.f / ((float)DIMN * (float)DIMN));
    for (int i = blk; i < DIMN; i += 8) {
        const float a = total - rs[i];
        const int len = DIMN - i;
        float* p = out + b * TRI + i * DIMN - ((i * (i - 1)) >> 1);
        const float* rsp = rs + i;
        int k = tid;
        for (; k + 768 < len; k += 1024) {
            float v0 = p[k], v1 = p[k + 256], v2 = p[k + 512], v3 = p[k + 768];
            p[k]       = v0 - rsp[k]       + a;
            p[k + 256] = v1 - rsp[k + 256] + a;
            p[k + 512] = v2 - rsp[k + 512] + a;
            p[k + 768] = v3 - rsp[k + 768] + a;
        }
        for (; k < len; k += 256) p[k] = p[k] - rsp[k] + a;
    }
}

extern "C" void kernel_launch(void* const* d_in, const int* in_sizes, int n_in,
                              void* d_out, int out_size) {
    const float* x = (const float*)d_in[0];
    const float* t = (const float*)d_in[1];
    float* out = (float*)d_out;

    const int smem = 2 * 128 * LDA * (int)sizeof(float);  // 110,592 B
    cudaFuncSetAttribute(k_bdc, cudaFuncAttributeMaxDynamicSharedMemorySize, smem);

    k_norms<<<(BATCH * DIMN) / 8, 256>>>(x);
    k_bdc<<<BATCH * 15, 256, smem>>>(x, t, out);
    k_total<<<BATCH, 256>>>();
    k_center<<<BATCH * 8, 256>>>(out);
}

// round 9
// speedup vs baseline: 1.4622x; 1.3519x over previous
#include <cuda_runtime.h>
#include <cuda_bf16.h>
#include <cstdint>

#define DIMN 640
#define BATCH 64
#define MSP 100
#define TRI 205120           // 640*641/2
#define LDA 108              // smem row stride for operands
#define LDT 132              // smem row stride for staged output tile
#define SQRT_EPS 0.0031622776601683794f

// -------- scratch (no allocations allowed) --------
__device__ float g_d[BATCH * DIMN];       // squared norms (exact fp32)
__device__ float g_rowsum[BATCH * DIMN];  // full-row sums of dcov

__device__ __forceinline__ unsigned f2tf32(float f) {
    unsigned u;
    asm("cvt.rna.tf32.f32 %0, %1;" : "=r"(u) : "f"(f));
    return u;
}
__device__ __forceinline__ float asqrt(float x) {
    float r;
    asm("sqrt.approx.f32 %0, %1;" : "=f"(r) : "f"(x));
    return r;
}
__device__ __forceinline__ void mma_tf32(float c[4], const unsigned a[4], const unsigned b[2]) {
    asm volatile(
        "mma.sync.aligned.m16n8k8.row.col.f32.tf32.tf32.f32 "
        "{%0,%1,%2,%3}, {%4,%5,%6,%7}, {%8,%9}, {%0,%1,%2,%3};"
        : "+f"(c[0]), "+f"(c[1]), "+f"(c[2]), "+f"(c[3])
        : "r"(a[0]), "r"(a[1]), "r"(a[2]), "r"(a[3]), "r"(b[0]), "r"(b[1]));
}

// ---------------- Kernel 0: exact squared norms + zero rowsums ----------------
__global__ void k_norms(const float* __restrict__ x) {
    int warp = blockIdx.x * 8 + (threadIdx.x >> 5);
    int lane = threadIdx.x & 31;
    if (warp >= BATCH * DIMN) return;
    const float* p = x + (size_t)warp * MSP;
    float s = 0.f;
    for (int m = lane; m < MSP; m += 32) {
        float v = p[m];
        s = fmaf(v, v, s);
    }
    #pragma unroll
    for (int o = 16; o > 0; o >>= 1) s += __shfl_xor_sync(0xffffffffu, s, o);
    if (lane == 0) {
        g_d[warp] = s;
        g_rowsum[warp] = 0.f;
    }
}

// ---------------- Kernel 1: tf32 Gram tiles + fused BDC epilogue ----------------
__global__ void __launch_bounds__(256, 2)
k_bdc(const float* __restrict__ x, const float* __restrict__ tptr, float* __restrict__ out) {
    extern __shared__ float smem[];
    float* As = smem;                 // [128][LDA]
    float* Bs = smem + 128 * LDA;     // [128][LDA]
    float* Ts = smem;                 // staged output tile [128][LDT], reused after MMA
    __shared__ float rssh[128];
    __shared__ float cssh[128];

    const int tid = threadIdx.x;
    int b = blockIdx.x / 15;
    int p = blockIdx.x % 15;
    int ti = 0;
    while (p >= 5 - ti) { p -= 5 - ti; ti++; }
    int tj = ti + p;
    const bool diag = (ti == tj);

    // load tiles (tf32-converted), K padded with zeros to 104
    const float* xa = x + (size_t)(b * DIMN + ti * 128) * MSP;
    const float* xb = x + (size_t)(b * DIMN + tj * 128) * MSP;
    for (int idx = tid; idx < 128 * MSP; idx += 256) {
        int r = idx / MSP;
        int m = idx - r * MSP;
        As[r * LDA + m] = __uint_as_float(f2tf32(xa[idx]));
        if (!diag) Bs[r * LDA + m] = __uint_as_float(f2tf32(xb[idx]));
    }
    for (int idx = tid; idx < 128 * 4; idx += 256) {
        int r = idx >> 2, c = idx & 3;
        As[r * LDA + MSP + c] = 0.f;
        if (!diag) Bs[r * LDA + MSP + c] = 0.f;
    }
    if (tid < 128) rssh[tid] = 0.f;
    else cssh[tid - 128] = 0.f;
    __syncthreads();

    const float* Bse = diag ? As : Bs;

    const int lane = tid & 31;
    const int w = tid >> 5;
    const int wm = (w >> 2) * 64;   // warp m-offset (2 warps in m)
    const int wn = (w & 3) * 32;    // warp n-offset (4 warps in n)
    const int g = lane >> 2;        // 0..7
    const int tg = lane & 3;        // 0..3

    float acc[4][4][4];
    #pragma unroll
    for (int am = 0; am < 4; am++)
        #pragma unroll
        for (int an = 0; an < 4; an++)
            #pragma unroll
            for (int v = 0; v < 4; v++) acc[am][an][v] = 0.f;

    #pragma unroll
    for (int ks = 0; ks < 13; ks++) {
        const int k0 = ks * 8;
        unsigned a[4][4], bf[4][2];
        #pragma unroll
        for (int am = 0; am < 4; am++) {
            const float* r0 = &As[(wm + am * 16 + g) * LDA + k0 + tg];
            const float* r1 = &As[(wm + am * 16 + g + 8) * LDA + k0 + tg];
            a[am][0] = __float_as_uint(r0[0]);
            a[am][1] = __float_as_uint(r1[0]);
            a[am][2] = __float_as_uint(r0[4]);
            a[am][3] = __float_as_uint(r1[4]);
        }
        #pragma unroll
        for (int an = 0; an < 4; an++) {
            const float* br = &Bse[(wn + an * 8 + g) * LDA + k0 + tg];
            bf[an][0] = __float_as_uint(br[0]);
            bf[an][1] = __float_as_uint(br[4]);
        }
        #pragma unroll
        for (int am = 0; am < 4; am++)
            #pragma unroll
            for (int an = 0; an < 4; an++) mma_tf32(acc[am][an], a[am], bf[an]);
    }

    // ---- epilogue: dcov transform, stage into smem tile ----
    const float s = expf(tptr[0]);
    float drow[8], dcol[8];
    const int rbase = b * DIMN + ti * 128 + wm;
    const int cbase = b * DIMN + tj * 128 + wn;
    #pragma unroll
    for (int am = 0; am < 4; am++) {
        drow[2 * am]     = g_d[rbase + am * 16 + g];
        drow[2 * am + 1] = g_d[rbase + am * 16 + g + 8];
    }
    #pragma unroll
    for (int an = 0; an < 4; an++) {
        dcol[2 * an]     = g_d[cbase + an * 8 + 2 * tg];
        dcol[2 * an + 1] = g_d[cbase + an * 8 + 2 * tg + 1];
    }

    float rp[8], cp[8];
    #pragma unroll
    for (int q = 0; q < 8; q++) { rp[q] = 0.f; cp[q] = 0.f; }

    __syncthreads();   // all warps done reading As/Bs; safe to overwrite with Ts

    #pragma unroll
    for (int am = 0; am < 4; am++) {
        #pragma unroll
        for (int an = 0; an < 4; an++) {
            #pragma unroll
            for (int v = 0; v < 4; v++) {
                const int hi = v >> 1, lo = v & 1;
                const int r = wm + am * 16 + g + hi * 8;   // local row in tile
                const int c = wn + an * 8 + 2 * tg + lo;   // local col in tile
                float q2 = drow[2 * am + hi] + dcol[2 * an + lo] - 2.f * acc[am][an][v];
                q2 = fmaxf(q2, 0.f);
                float val = asqrt(fmaf(q2, s, 1e-5f));
                if (diag) {
                    if (c == r) val = SQRT_EPS;
                    if (c > r) { rp[2 * am + hi] += val; cp[2 * an + lo] += val; }
                    else if (c == r) rp[2 * am + hi] += val;
                } else {
                    rp[2 * am + hi] += val;
                    cp[2 * an + lo] += val;
                }
                Ts[r * LDT + c] = val;
            }
        }
    }
    __syncthreads();

    // ---- coalesced stores from staged tile ----
    const int ob = b * TRI;
    const int lane128 = tid & 127;
    if (!diag) {
        #pragma unroll 4
        for (int r = tid >> 7; r < 128; r += 2) {
            const int gi = ti * 128 + r;
            const int gj = tj * 128 + lane128;
            const int rowoff = gi * (DIMN - 1) - ((gi * (gi - 1)) >> 1);  // row start minus gi
            out[ob + rowoff + gj] = Ts[r * LDT + lane128];
        }
    } else {
        #pragma unroll 4
        for (int r = tid >> 7; r < 128; r += 2) {
            const int gi = ti * 128 + r;
            const int rowoff = gi * (DIMN - 1) - ((gi * (gi - 1)) >> 1);
            const int c = r + lane128;
            if (c < 128)
                out[ob + rowoff + ti * 128 + c] = Ts[r * LDT + c];
        }
    }

    // ---- row/col sum reductions ----
    #pragma unroll
    for (int q = 0; q < 8; q++) {
        float r = rp[q];
        r += __shfl_xor_sync(0xffffffffu, r, 1);
        r += __shfl_xor_sync(0xffffffffu, r, 2);
        if (tg == 0) atomicAdd(&rssh[wm + (q >> 1) * 16 + g + (q & 1) * 8], r);
    }
    #pragma unroll
    for (int q = 0; q < 8; q++) {
        float c = cp[q];
        c += __shfl_xor_sync(0xffffffffu, c, 4);
        c += __shfl_xor_sync(0xffffffffu, c, 8);
        c += __shfl_xor_sync(0xffffffffu, c, 16);
        if (g == 0) atomicAdd(&cssh[wn + (q >> 1) * 8 + 2 * tg + (q & 1)], c);
    }
    __syncthreads();
    if (tid < 128) atomicAdd(&g_rowsum[b * DIMN + ti * 128 + tid], rssh[tid]);
    else atomicAdd(&g_rowsum[b * DIMN + tj * 128 + (tid - 128)], cssh[tid - 128]);
}

// ---------------- Kernel 2: double centering, 64 blocks/batch, fused total ----------------
__global__ void __launch_bounds__(256)
k_center(float* __restrict__ out) {
    __shared__ float rs[DIMN];
    __shared__ float red[8];
    const int b = blockIdx.x >> 6;
    const int blk = blockIdx.x & 63;      // 0..63
    const int tid = threadIdx.x;
    const float inv = 1.f / (float)DIMN;

    for (int i = tid; i < DIMN; i += 256) rs[i] = g_rowsum[b * DIMN + i] * inv;
    __syncthreads();

    // fused grand total: sum(rs)/D == grand_sum/D^2
    {
        float s = rs[tid] + rs[tid + 256];
        if (tid < DIMN - 512) s += rs[tid + 512];
        #pragma unroll
        for (int o = 16; o > 0; o >>= 1) s += __shfl_xor_sync(0xffffffffu, s, o);
        if ((tid & 31) == 0) red[tid >> 5] = s;
    }
    __syncthreads();
    const float total = (red[0] + red[1] + red[2] + red[3] +
                         red[4] + red[5] + red[6] + red[7]) * inv;

    float* ob = out + (size_t)b * TRI;
    #pragma unroll
    for (int q = 0; q < 5; q++) {
        const int p1 = blk + 64 * q;          // pair index 0..319
        const int i1 = p1;                    // long row, len 640-p1
        const int i2 = DIMN - 1 - p1;         // short row, len p1+1 (<=320)
        const int len1 = DIMN - i1;
        const int len2 = DIMN - i2;
        const float a1 = total - rs[i1];
        const float a2 = total - rs[i2];
        float* r1p = ob + i1 * DIMN - ((i1 * (i1 - 1)) >> 1);
        float* r2p = ob + i2 * DIMN - ((i2 * (i2 - 1)) >> 1);

        const int k0 = tid, k1 = tid + 256, k2 = tid + 512;
        const bool m0 = k0 < len1, m1 = k1 < len1, m2 = k2 < len1;
        const bool n0 = k0 < len2, n1 = k1 < len2;
        float v0 = 0.f, v1 = 0.f, v2 = 0.f, w0 = 0.f, w1 = 0.f;
        if (m0) v0 = r1p[k0];
        if (m1) v1 = r1p[k1];
        if (m2) v2 = r1p[k2];
        if (n0) w0 = r2p[k0];
        if (n1) w1 = r2p[k1];
        if (m0) r1p[k0] = v0 - rs[i1 + k0] + a1;
        if (m1) r1p[k1] = v1 - rs[i1 + k1] + a1;
        if (m2) r1p[k2] = v2 - rs[i1 + k2] + a1;
        if (n0) r2p[k0] = w0 - rs[i2 + k0] + a2;
        if (n1) r2p[k1] = w1 - rs[i2 + k1] + a2;
    }
}

extern "C" void kernel_launch(void* const* d_in, const int* in_sizes, int n_in,
                              void* d_out, int out_size) {
    const float* x = (const float*)d_in[0];
    const float* t = (const float*)d_in[1];
    float* out = (float*)d_out;

    const int smem = 2 * 128 * LDA * (int)sizeof(float);  // 110,592 B
    cudaFuncSetAttribute(k_bdc, cudaFuncAttributeMaxDynamicSharedMemorySize, smem);

    k_norms<<<(BATCH * DIMN) / 8, 256>>>(x);
    k_bdc<<<BATCH * 15, 256, smem>>>(x, t, out);
    k_center<<<BATCH * 64, 256>>>(out);
}

// round 11
// speedup vs baseline: 1.5059x; 1.0299x over previous
#include <cuda_runtime.h>
#include <cuda_bf16.h>
#include <cstdint>

#define DIMN 640
#define BATCH 64
#define MSP 100
#define TRI 205120           // 640*641/2
#define LDA 108              // smem row stride for operands
#define LDT 132              // smem row stride for staged output tile
#define SQRT_EPS 0.0031622776601683794f

// -------- scratch: collision-free partial row sums, rewritten fully each launch --------
__device__ float g_part[BATCH * 5 * DIMN];

__device__ __forceinline__ unsigned f2tf32(float f) {
    unsigned u;
    asm("cvt.rna.tf32.f32 %0, %1;" : "=r"(u) : "f"(f));
    return u;
}
__device__ __forceinline__ float asqrt(float x) {
    float r;
    asm("sqrt.approx.f32 %0, %1;" : "=f"(r) : "f"(x));
    return r;
}
__device__ __forceinline__ void mma_tf32(float c[4], const unsigned a[4], const unsigned b[2]) {
    asm volatile(
        "mma.sync.aligned.m16n8k8.row.col.f32.tf32.tf32.f32 "
        "{%0,%1,%2,%3}, {%4,%5,%6,%7}, {%8,%9}, {%0,%1,%2,%3};"
        : "+f"(c[0]), "+f"(c[1]), "+f"(c[2]), "+f"(c[3])
        : "r"(a[0]), "r"(a[1]), "r"(a[2]), "r"(a[3]), "r"(b[0]), "r"(b[1]));
}

// ---------------- Kernel 1: tf32 Gram tiles + fused norms + BDC epilogue ----------------
__global__ void __launch_bounds__(256, 2)
k_bdc(const float* __restrict__ x, const float* __restrict__ tptr, float* __restrict__ out) {
    extern __shared__ float smem[];
    float* As = smem;                 // [128][LDA]
    float* Bs = smem + 128 * LDA;     // [128][LDA]
    float* Ts = smem;                 // staged output tile [128][LDT], reused after MMA
    __shared__ float rssh[128];
    __shared__ float cssh[128];
    __shared__ float dAs[128];        // tf32-consistent squared norms, A rows
    __shared__ float dBs[128];        // same, B rows

    const int tid = threadIdx.x;
    int b = blockIdx.x / 15;
    int p = blockIdx.x % 15;
    int ti = 0;
    while (p >= 5 - ti) { p -= 5 - ti; ti++; }
    int tj = ti + p;
    const bool diag = (ti == tj);

    // load tiles (tf32-converted), K padded with zeros to 104
    const float* xa = x + (size_t)(b * DIMN + ti * 128) * MSP;
    const float* xb = x + (size_t)(b * DIMN + tj * 128) * MSP;
    for (int idx = tid; idx < 128 * MSP; idx += 256) {
        int r = idx / MSP;
        int m = idx - r * MSP;
        As[r * LDA + m] = __uint_as_float(f2tf32(xa[idx]));
        if (!diag) Bs[r * LDA + m] = __uint_as_float(f2tf32(xb[idx]));
    }
    for (int idx = tid; idx < 128 * 4; idx += 256) {
        int r = idx >> 2, c = idx & 3;
        As[r * LDA + MSP + c] = 0.f;
        if (!diag) Bs[r * LDA + MSP + c] = 0.f;
    }
    if (tid < 128) rssh[tid] = 0.f;
    else cssh[tid - 128] = 0.f;
    __syncthreads();

    // ---- in-kernel norms from the tf32 smem tiles (conflict-free float4 reads) ----
    if (tid < 128) {
        const float4* rowp = (const float4*)(As + tid * LDA);
        float s = 0.f;
        #pragma unroll
        for (int m = 0; m < 25; m++) {
            float4 v = rowp[m];
            s = fmaf(v.x, v.x, fmaf(v.y, v.y, fmaf(v.z, v.z, fmaf(v.w, v.w, s))));
        }
        dAs[tid] = s;
    } else if (!diag) {
        const float4* rowp = (const float4*)(Bs + (tid - 128) * LDA);
        float s = 0.f;
        #pragma unroll
        for (int m = 0; m < 25; m++) {
            float4 v = rowp[m];
            s = fmaf(v.x, v.x, fmaf(v.y, v.y, fmaf(v.z, v.z, fmaf(v.w, v.w, s))));
        }
        dBs[tid - 128] = s;
    }
    // no sync needed before MMA: MMA reads As/Bs (ready); norms are read-only here.

    const float* Bse = diag ? As : Bs;
    const float* dBse = diag ? dAs : dBs;

    const int lane = tid & 31;
    const int w = tid >> 5;
    const int wm = (w >> 2) * 64;   // warp m-offset (2 warps in m)
    const int wn = (w & 3) * 32;    // warp n-offset (4 warps in n)
    const int g = lane >> 2;        // 0..7
    const int tg = lane & 3;        // 0..3

    float acc[4][4][4];
    #pragma unroll
    for (int am = 0; am < 4; am++)
        #pragma unroll
        for (int an = 0; an < 4; an++)
            #pragma unroll
            for (int v = 0; v < 4; v++) acc[am][an][v] = 0.f;

    #pragma unroll
    for (int ks = 0; ks < 13; ks++) {
        const int k0 = ks * 8;
        unsigned a[4][4], bf[4][2];
        #pragma unroll
        for (int am = 0; am < 4; am++) {
            const float* r0 = &As[(wm + am * 16 + g) * LDA + k0 + tg];
            const float* r1 = &As[(wm + am * 16 + g + 8) * LDA + k0 + tg];
            a[am][0] = __float_as_uint(r0[0]);
            a[am][1] = __float_as_uint(r1[0]);
            a[am][2] = __float_as_uint(r0[4]);
            a[am][3] = __float_as_uint(r1[4]);
        }
        #pragma unroll
        for (int an = 0; an < 4; an++) {
            const float* br = &Bse[(wn + an * 8 + g) * LDA + k0 + tg];
            bf[an][0] = __float_as_uint(br[0]);
            bf[an][1] = __float_as_uint(br[4]);
        }
        #pragma unroll
        for (int am = 0; am < 4; am++)
            #pragma unroll
            for (int an = 0; an < 4; an++) mma_tf32(acc[am][an], a[am], bf[an]);
    }

    __syncthreads();   // norms written by all warps; operand reads done -> Ts may overwrite

    // ---- epilogue: dcov transform, stage into smem tile ----
    const float s = expf(tptr[0]);
    float drow[8], dcol[8];
    #pragma unroll
    for (int am = 0; am < 4; am++) {
        drow[2 * am]     = dAs[wm + am * 16 + g];
        drow[2 * am + 1] = dAs[wm + am * 16 + g + 8];
    }
    #pragma unroll
    for (int an = 0; an < 4; an++) {
        dcol[2 * an]     = dBse[wn + an * 8 + 2 * tg];
        dcol[2 * an + 1] = dBse[wn + an * 8 + 2 * tg + 1];
    }

    float rp[8], cp[8];
    #pragma unroll
    for (int q = 0; q < 8; q++) { rp[q] = 0.f; cp[q] = 0.f; }

    #pragma unroll
    for (int am = 0; am < 4; am++) {
        #pragma unroll
        for (int an = 0; an < 4; an++) {
            #pragma unroll
            for (int v = 0; v < 4; v++) {
                const int hi = v >> 1, lo = v & 1;
                const int r = wm + am * 16 + g + hi * 8;   // local row in tile
                const int c = wn + an * 8 + 2 * tg + lo;   // local col in tile
                float q2 = drow[2 * am + hi] + dcol[2 * an + lo] - 2.f * acc[am][an][v];
                q2 = fmaxf(q2, 0.f);
                float val = asqrt(fmaf(q2, s, 1e-5f));
                if (diag) {
                    if (c == r) val = SQRT_EPS;
                    if (c > r) { rp[2 * am + hi] += val; cp[2 * an + lo] += val; }
                    else if (c == r) rp[2 * am + hi] += val;
                } else {
                    rp[2 * am + hi] += val;
                    cp[2 * an + lo] += val;
                }
                Ts[r * LDT + c] = val;
            }
        }
    }
    __syncthreads();

    // ---- coalesced stores from staged tile ----
    const int ob = b * TRI;
    const int lane128 = tid & 127;
    if (!diag) {
        #pragma unroll 4
        for (int r = tid >> 7; r < 128; r += 2) {
            const int gi = ti * 128 + r;
            const int gj = tj * 128 + lane128;
            const int rowoff = gi * (DIMN - 1) - ((gi * (gi - 1)) >> 1);  // row start minus gi
            out[ob + rowoff + gj] = Ts[r * LDT + lane128];
        }
    } else {
        #pragma unroll 4
        for (int r = tid >> 7; r < 128; r += 2) {
            const int gi = ti * 128 + r;
            const int rowoff = gi * (DIMN - 1) - ((gi * (gi - 1)) >> 1);
            const int c = r + lane128;
            if (c < 128)
                out[ob + rowoff + ti * 128 + c] = Ts[r * LDT + c];
        }
    }

    // ---- row/col sum reductions into smem ----
    #pragma unroll
    for (int q = 0; q < 8; q++) {
        float r = rp[q];
        r += __shfl_xor_sync(0xffffffffu, r, 1);
        r += __shfl_xor_sync(0xffffffffu, r, 2);
        if (tg == 0) atomicAdd(&rssh[wm + (q >> 1) * 16 + g + (q & 1) * 8], r);
    }
    #pragma unroll
    for (int q = 0; q < 8; q++) {
        float c = cp[q];
        c += __shfl_xor_sync(0xffffffffu, c, 4);
        c += __shfl_xor_sync(0xffffffffu, c, 8);
        c += __shfl_xor_sync(0xffffffffu, c, 16);
        if (g == 0) atomicAdd(&cssh[wn + (q >> 1) * 8 + 2 * tg + (q & 1)], c);
    }
    __syncthreads();

    // ---- collision-free partial-sum writes (no global atomics, no pre-zeroing) ----
    if (!diag) {
        if (tid < 128)
            g_part[(b * 5 + tj) * DIMN + ti * 128 + tid] = rssh[tid];
        else
            g_part[(b * 5 + ti) * DIMN + tj * 128 + (tid - 128)] = cssh[tid - 128];
    } else {
        if (tid < 128)
            g_part[(b * 5 + ti) * DIMN + ti * 128 + tid] = rssh[tid] + cssh[tid];
    }
}

// ---------------- Kernel 2: double centering, 64 blocks/batch, fused total ----------------
__global__ void __launch_bounds__(256)
k_center(float* __restrict__ out) {
    __shared__ float rs[DIMN];
    __shared__ float red[8];
    const int b = blockIdx.x >> 6;
    const int blk = blockIdx.x & 63;      // 0..63
    const int tid = threadIdx.x;
    const float inv = 1.f / (float)DIMN;

    const float* gp = &g_part[b * 5 * DIMN];
    for (int i = tid; i < DIMN; i += 256) {
        float s = gp[i] + gp[DIMN + i] + gp[2 * DIMN + i]
                + gp[3 * DIMN + i] + gp[4 * DIMN + i];
        rs[i] = s * inv;
    }
    __syncthreads();

    // fused grand total: sum(rs)/D == grand_sum/D^2
    {
        float s = rs[tid] + rs[tid + 256];
        if (tid < DIMN - 512) s += rs[tid + 512];
        #pragma unroll
        for (int o = 16; o > 0; o >>= 1) s += __shfl_xor_sync(0xffffffffu, s, o);
        if ((tid & 31) == 0) red[tid >> 5] = s;
    }
    __syncthreads();
    const float total = (red[0] + red[1] + red[2] + red[3] +
                         red[4] + red[5] + red[6] + red[7]) * inv;

    float* ob = out + (size_t)b * TRI;
    #pragma unroll
    for (int q = 0; q < 5; q++) {
        const int p1 = blk + 64 * q;          // pair index 0..319
        const int i1 = p1;                    // long row, len 640-p1
        const int i2 = DIMN - 1 - p1;         // short row, len p1+1 (<=320)
        const int len1 = DIMN - i1;
        const int len2 = DIMN - i2;
        const float a1 = total - rs[i1];
        const float a2 = total - rs[i2];
        float* r1p = ob + i1 * DIMN - ((i1 * (i1 - 1)) >> 1);
        float* r2p = ob + i2 * DIMN - ((i2 * (i2 - 1)) >> 1);

        const int k0 = tid, k1 = tid + 256, k2 = tid + 512;
        const bool m0 = k0 < len1, m1 = k1 < len1, m2 = k2 < len1;
        const bool n0 = k0 < len2, n1 = k1 < len2;
        float v0 = 0.f, v1 = 0.f, v2 = 0.f, w0 = 0.f, w1 = 0.f;
        if (m0) v0 = r1p[k0];
        if (m1) v1 = r1p[k1];
        if (m2) v2 = r1p[k2];
        if (n0) w0 = r2p[k0];
        if (n1) w1 = r2p[k1];
        if (m0) r1p[k0] = v0 - rs[i1 + k0] + a1;
        if (m1) r1p[k1] = v1 - rs[i1 + k1] + a1;
        if (m2) r1p[k2] = v2 - rs[i1 + k2] + a1;
        if (n0) r2p[k0] = w0 - rs[i2 + k0] + a2;
        if (n1) r2p[k1] = w1 - rs[i2 + k1] + a2;
    }
}

extern "C" void kernel_launch(void* const* d_in, const int* in_sizes, int n_in,
                              void* d_out, int out_size) {
    const float* x = (const float*)d_in[0];
    const float* t = (const float*)d_in[1];
    float* out = (float*)d_out;

    const int smem = 2 * 128 * LDA * (int)sizeof(float);  // 110,592 B
    cudaFuncSetAttribute(k_bdc, cudaFuncAttributeMaxDynamicSharedMemorySize, smem);

    k_bdc<<<BATCH * 15, 256, smem>>>(x, t, out);
    k_center<<<BATCH * 64, 256>>>(out);
}